// round 1
// baseline (speedup 1.0000x reference)
#include <cuda_runtime.h>
#include <cuda_bf16.h>

#define BB 8
#define LL 4096
#define DD 1024
#define CC 128

// Boundary positions per batch: we need starts of chunks 0..127 plus the end
// position of chunk 127 (the 128th boundary) when more boundaries exist.
__device__ int g_pos[BB][CC + 2];
__device__ int g_nb[BB];

// ---------------------------------------------------------------------------
// Kernel 1: per-batch scan of boundary flags -> boundary positions.
// One block per batch, 256 threads, 16 tokens each (L=4096).
// ---------------------------------------------------------------------------
__global__ void seg_scan_kernel(const float* __restrict__ boundaries) {
    const int b = blockIdx.x;
    const float* bp = boundaries + (size_t)b * LL;
    const int t = threadIdx.x;          // 0..255
    const int base = t * 16;

    __shared__ int cnts[256];
    __shared__ int offs[256];

    unsigned flags = 0;
    int local = 0;
#pragma unroll
    for (int i = 0; i < 16; i++) {
        if (bp[base + i] > 0.5f) { flags |= (1u << i); local++; }
    }
    cnts[t] = local;
    __syncthreads();

    if (t == 0) {
        int s = 0;
        for (int i = 0; i < 256; i++) { offs[i] = s; s += cnts[i]; }
        g_nb[b] = s;
    }
    __syncthreads();

    int idx = offs[t];
#pragma unroll
    for (int i = 0; i < 16; i++) {
        if (flags & (1u << i)) {
            if (idx <= CC) g_pos[b][idx] = base + i;   // store positions 0..128
            idx++;
        }
    }
}

// ---------------------------------------------------------------------------
// Kernel 2: one block per (batch, chunk). 256 threads; thread t owns float4
// column t (256 * 4 = 1024 = D). Streams the contiguous token range of the
// chunk with coalesced float4 loads, accumulates in registers, writes mean.
// Deterministic: fixed serial order over tokens per column.
// ---------------------------------------------------------------------------
__global__ void pool_kernel(const float* __restrict__ x,
                            float* __restrict__ means,
                            float* __restrict__ cnts_out,
                            int write_cnts) {
    const int c = blockIdx.x;           // chunk 0..127
    const int b = blockIdx.y;           // batch 0..7
    const int t = threadIdx.x;          // 0..255

    const int nb = g_nb[b];
    const int valid = nb < CC ? nb : CC;

    float4 acc = make_float4(0.f, 0.f, 0.f, 0.f);
    int cnt = 0;

    if (c < valid) {
        const int s = g_pos[b][c];
        const int e = (c + 1 < nb) ? g_pos[b][c + 1] : LL;
        cnt = e - s;

        const float4* xp =
            reinterpret_cast<const float4*>(x + (size_t)b * LL * DD + (size_t)s * DD) + t;
        for (int l = s; l < e; ++l, xp += DD / 4) {
            float4 v = *xp;
            acc.x += v.x; acc.y += v.y; acc.z += v.z; acc.w += v.w;
        }
        const float inv = 1.0f / (float)cnt;
        acc.x *= inv; acc.y *= inv; acc.z *= inv; acc.w *= inv;
    }

    // Output is poisoned 0xAA: every (b,c) slot must be written, zeros for
    // empty/invalid chunks.
    reinterpret_cast<float4*>(means + ((size_t)b * CC + c) * DD)[t] = acc;

    if (write_cnts && t == 0) {
        cnts_out[b * CC + c] = (float)cnt;
    }
}

extern "C" void kernel_launch(void* const* d_in, const int* in_sizes, int n_in,
                              void* d_out, int out_size) {
    // Identify inputs by size (robust to ordering): x has B*L*D elements.
    const float* x = nullptr;
    const float* boundaries = nullptr;
    for (int i = 0; i < n_in; i++) {
        if (in_sizes[i] == BB * LL * DD) x = (const float*)d_in[i];
        else if (in_sizes[i] == BB * LL) boundaries = (const float*)d_in[i];
    }

    float* out = (float*)d_out;
    const int means_elems = BB * CC * DD;
    const int write_cnts = (out_size > means_elems) ? 1 : 0;

    seg_scan_kernel<<<BB, 256>>>(boundaries);
    pool_kernel<<<dim3(CC, BB), 256>>>(x, out, out + means_elems, write_cnts);
}

// round 2
// speedup vs baseline: 1.2165x; 1.2165x over previous
#include <cuda_runtime.h>
#include <cuda_bf16.h>

#define BB 8
#define LL 4096
#define DD 1024
#define CC 128
#define SLICE 32
#define MAXSL (LL / SLICE + CC)   // 256: upper bound on slices per batch

// Per-batch chunk metadata
__device__ int g_nsl[BB];                 // number of slices
__device__ int g_chunk_cnt[BB][CC];       // token count per chunk (0 => empty)
__device__ int g_chunk_start[BB][CC];     // first slice index of chunk
__device__ int g_chunk_nsl[BB][CC];       // slice count of chunk
__device__ int g_slice_s[BB][MAXSL];      // slice token start
__device__ int g_slice_e[BB][MAXSL];      // slice token end (exclusive)

// Partial sums scratch: 8 * 256 * 256 float4 = 8 MB
__device__ float4 g_part[BB][MAXSL][DD / 4];

// ---------------------------------------------------------------------------
// Kernel 1: per-batch boundary scan -> chunk ranges -> slice list.
// One block per batch, 256 threads (16 tokens each).
// ---------------------------------------------------------------------------
__global__ void seg_scan_kernel(const float* __restrict__ boundaries) {
    const int b = blockIdx.x;
    const float* bp = boundaries + (size_t)b * LL;
    const int t = threadIdx.x;          // 0..255
    const int base = t * 16;

    __shared__ int cnts[256];
    __shared__ int offs[256];
    __shared__ int pos[CC + 1];         // boundary positions 0..128
    __shared__ int snb;
    __shared__ int nsl_c[CC];
    __shared__ int soff[CC];

    unsigned flags = 0;
    int local = 0;
#pragma unroll
    for (int i = 0; i < 16; i++) {
        if (bp[base + i] > 0.5f) { flags |= (1u << i); local++; }
    }
    cnts[t] = local;
    __syncthreads();

    if (t == 0) {
        int s = 0;
        for (int i = 0; i < 256; i++) { offs[i] = s; s += cnts[i]; }
        snb = s;
    }
    __syncthreads();

    {
        int idx = offs[t];
#pragma unroll
        for (int i = 0; i < 16; i++) {
            if (flags & (1u << i)) {
                if (idx <= CC) pos[idx] = base + i;
                idx++;
            }
        }
    }
    __syncthreads();

    const int nb = snb;
    const int valid = nb < CC ? nb : CC;

    int s0 = 0, e0 = 0, len = 0;
    if (t < CC) {
        if (t < valid) {
            s0 = pos[t];
            e0 = (t + 1 < nb) ? pos[t + 1] : LL;   // t+1 <= CC always here
            len = e0 - s0;
            nsl_c[t] = (len + SLICE - 1) / SLICE;
        } else {
            nsl_c[t] = 0;
        }
    }
    __syncthreads();

    if (t == 0) {
        int s = 0;
        for (int c = 0; c < CC; c++) { soff[c] = s; s += nsl_c[c]; }
        g_nsl[b] = s;
    }
    __syncthreads();

    if (t < CC) {
        g_chunk_cnt[b][t]   = (t < valid) ? len : 0;
        g_chunk_start[b][t] = soff[t];
        g_chunk_nsl[b][t]   = (t < valid) ? nsl_c[t] : 0;
        if (t < valid) {
            int si = soff[t];
            for (int ss = s0; ss < e0; ss += SLICE, si++) {
                g_slice_s[b][si] = ss;
                int ee = ss + SLICE;
                g_slice_e[b][si] = ee < e0 ? ee : e0;
            }
        }
    }
}

// ---------------------------------------------------------------------------
// Kernel 2 (bandwidth pass): one block per (batch, slice). 256 threads;
// thread t owns float4 column t. Trip count <= 32, unrolled for MLP.
// All blocks do <= 128 KB -> perfectly balanced.
// ---------------------------------------------------------------------------
__global__ void partial_kernel(const float* __restrict__ x) {
    const int sl = blockIdx.x;
    const int b  = blockIdx.y;
    const int t  = threadIdx.x;

    if (sl >= g_nsl[b]) return;

    const int s = g_slice_s[b][sl];
    const int e = g_slice_e[b][sl];
    const int n = e - s;

    const float4* __restrict__ xp =
        reinterpret_cast<const float4*>(x + (size_t)b * LL * DD) +
        (size_t)s * (DD / 4) + t;

    float4 a0 = make_float4(0.f, 0.f, 0.f, 0.f);
    float4 a1 = make_float4(0.f, 0.f, 0.f, 0.f);

    int i = 0;
#pragma unroll 4
    for (; i + 1 < n; i += 2) {
        float4 v0 = xp[(size_t)i * (DD / 4)];
        float4 v1 = xp[(size_t)(i + 1) * (DD / 4)];
        a0.x += v0.x; a0.y += v0.y; a0.z += v0.z; a0.w += v0.w;
        a1.x += v1.x; a1.y += v1.y; a1.z += v1.z; a1.w += v1.w;
    }
    if (i < n) {
        float4 v0 = xp[(size_t)i * (DD / 4)];
        a0.x += v0.x; a0.y += v0.y; a0.z += v0.z; a0.w += v0.w;
    }
    a0.x += a1.x; a0.y += a1.y; a0.z += a1.z; a0.w += a1.w;

    g_part[b][sl][t] = a0;
}

// ---------------------------------------------------------------------------
// Kernel 3: one block per (batch, chunk). Deterministic serial sum over the
// chunk's consecutive slice partials (avg ~2), divide, write. Zeros for
// empty/invalid chunks (output is poisoned).
// ---------------------------------------------------------------------------
__global__ void finalize_kernel(float* __restrict__ means,
                                float* __restrict__ cnts_out,
                                int write_cnts) {
    const int c = blockIdx.x;
    const int b = blockIdx.y;
    const int t = threadIdx.x;

    const int cnt = g_chunk_cnt[b][c];
    float4 acc = make_float4(0.f, 0.f, 0.f, 0.f);

    if (cnt > 0) {
        const int st = g_chunk_start[b][c];
        const int n  = g_chunk_nsl[b][c];
        for (int i = 0; i < n; i++) {
            float4 v = g_part[b][st + i][t];
            acc.x += v.x; acc.y += v.y; acc.z += v.z; acc.w += v.w;
        }
        const float inv = 1.0f / (float)cnt;
        acc.x *= inv; acc.y *= inv; acc.z *= inv; acc.w *= inv;
    }

    reinterpret_cast<float4*>(means + ((size_t)b * CC + c) * DD)[t] = acc;

    if (write_cnts && t == 0) {
        cnts_out[b * CC + c] = (float)cnt;
    }
}

extern "C" void kernel_launch(void* const* d_in, const int* in_sizes, int n_in,
                              void* d_out, int out_size) {
    const float* x = nullptr;
    const float* boundaries = nullptr;
    for (int i = 0; i < n_in; i++) {
        if (in_sizes[i] == BB * LL * DD) x = (const float*)d_in[i];
        else if (in_sizes[i] == BB * LL) boundaries = (const float*)d_in[i];
    }

    float* out = (float*)d_out;
    const int means_elems = BB * CC * DD;
    const int write_cnts = (out_size > means_elems) ? 1 : 0;

    seg_scan_kernel<<<BB, 256>>>(boundaries);
    partial_kernel<<<dim3(MAXSL, BB), 256>>>(x);
    finalize_kernel<<<dim3(CC, BB), 256>>>(out, out + means_elems, write_cnts);
}

// round 3
// speedup vs baseline: 1.4436x; 1.1866x over previous
#include <cuda_runtime.h>
#include <cuda_bf16.h>

#define BB 8
#define LL 4096
#define DD 1024
#define CC 128
#define SLICE 32
#define MAXSL (LL / SLICE + CC)   // 256: upper bound on slices per batch

// Per-batch chunk metadata
__device__ int g_nsl[BB];                 // number of slices
__device__ int g_chunk_cnt[BB][CC];       // token count per chunk (0 => empty)
__device__ int g_chunk_start[BB][CC];     // first slice index of chunk
__device__ int g_chunk_nsl[BB][CC];       // slice count of chunk
__device__ int g_slice_s[BB][MAXSL];      // slice token start
__device__ int g_slice_e[BB][MAXSL];      // slice token end (exclusive)

// Partial sums scratch: 8 * 256 * 256 float4 = 8 MB
__device__ float4 g_part[BB][MAXSL][DD / 4];

// ---------------------------------------------------------------------------
// Kernel 1: per-batch boundary scan -> chunk ranges -> slice list.
// One block per batch, 512 threads (8 tokens each). All scans are
// hierarchical warp scans — no serial smem chains.
// ---------------------------------------------------------------------------
__global__ void seg_scan_kernel(const float* __restrict__ boundaries) {
    const int b = blockIdx.x;
    const float* bp = boundaries + (size_t)b * LL;
    const int t    = threadIdx.x;       // 0..511
    const int lane = t & 31;
    const int wid  = t >> 5;            // 0..15

    __shared__ int wsum[16];            // per-warp boundary counts
    __shared__ int wexcl[16];           // exclusive offsets of warps
    __shared__ int pos[CC + 1];         // boundary positions 0..128
    __shared__ int snb;
    __shared__ int csum[4];             // per-warp slice-count sums (chunk phase)
    __shared__ int cexcl[4];

    // --- phase 1: flags + ordered compaction of boundary positions ---
    const int base = t * 8;
    unsigned flags = 0;
    {
        const float4* bp4 = reinterpret_cast<const float4*>(bp + base);
        float4 v0 = bp4[0];
        float4 v1 = bp4[1];
        if (v0.x > 0.5f) flags |= 1u;
        if (v0.y > 0.5f) flags |= 2u;
        if (v0.z > 0.5f) flags |= 4u;
        if (v0.w > 0.5f) flags |= 8u;
        if (v1.x > 0.5f) flags |= 16u;
        if (v1.y > 0.5f) flags |= 32u;
        if (v1.z > 0.5f) flags |= 64u;
        if (v1.w > 0.5f) flags |= 128u;
    }
    const int cnt = __popc(flags);

    // intra-warp inclusive scan of cnt
    int incl = cnt;
#pragma unroll
    for (int d = 1; d < 32; d <<= 1) {
        int v = __shfl_up_sync(0xFFFFFFFFu, incl, d);
        if (lane >= d) incl += v;
    }
    if (lane == 31) wsum[wid] = incl;
    __syncthreads();

    // warp 0 scans the 16 warp sums
    if (t < 16) {
        int v = wsum[t];
        int iv = v;
#pragma unroll
        for (int d = 1; d < 16; d <<= 1) {
            int u = __shfl_up_sync(0x0000FFFFu, iv, d);
            if (t >= d) iv += u;
        }
        wexcl[t] = iv - v;
        if (t == 15) snb = iv;
    }
    __syncthreads();

    {
        int idx = wexcl[wid] + (incl - cnt);   // exclusive offset of this thread
        unsigned f = flags;
        while (f) {
            int i = __ffs(f) - 1;
            f &= f - 1;
            if (idx <= CC) pos[idx] = base + i;
            idx++;
        }
    }
    __syncthreads();

    const int nb = snb;
    const int valid = nb < CC ? nb : CC;

    // --- phase 2: chunk ranges + slice-count scan (threads 0..127) ---
    int s0 = 0, e0 = 0, len = 0, nsl = 0;
    if (t < CC) {
        if (t < valid) {
            s0 = pos[t];
            e0 = (t + 1 < nb) ? pos[t + 1] : LL;
            len = e0 - s0;
            nsl = (len + SLICE - 1) / SLICE;
        }
    }

    // inclusive scan of nsl over threads 0..127 (4 warps)
    int cincl = nsl;
#pragma unroll
    for (int d = 1; d < 32; d <<= 1) {
        int v = __shfl_up_sync(0xFFFFFFFFu, cincl, d);
        if (lane >= d) cincl += v;
    }
    if (t < CC && lane == 31) csum[wid] = cincl;
    __syncthreads();

    if (t < 4) {
        int v = csum[t];
        int iv = v;
#pragma unroll
        for (int d = 1; d < 4; d <<= 1) {
            int u = __shfl_up_sync(0x0000000Fu, iv, d);
            if (t >= d) iv += u;
        }
        cexcl[t] = iv - v;
        if (t == 3) g_nsl[b] = iv;
    }
    __syncthreads();

    if (t < CC) {
        const int soff = cexcl[wid] + (cincl - nsl);
        g_chunk_cnt[b][t]   = len;
        g_chunk_start[b][t] = soff;
        g_chunk_nsl[b][t]   = nsl;
        if (len > 0) {
            int si = soff;
            for (int ss = s0; ss < e0; ss += SLICE, si++) {
                g_slice_s[b][si] = ss;
                int ee = ss + SLICE;
                g_slice_e[b][si] = ee < e0 ? ee : e0;
            }
        }
    }
}

// ---------------------------------------------------------------------------
// Kernel 2 (bandwidth pass): one block per (batch, slice). 256 threads;
// thread t owns float4 column t. Trip count <= 32, unrolled for MLP.
// All blocks do <= 128 KB -> perfectly balanced.
// ---------------------------------------------------------------------------
__global__ void partial_kernel(const float* __restrict__ x) {
    const int sl = blockIdx.x;
    const int b  = blockIdx.y;
    const int t  = threadIdx.x;

    if (sl >= g_nsl[b]) return;

    const int s = g_slice_s[b][sl];
    const int e = g_slice_e[b][sl];
    const int n = e - s;

    const float4* __restrict__ xp =
        reinterpret_cast<const float4*>(x + (size_t)b * LL * DD) +
        (size_t)s * (DD / 4) + t;

    float4 a0 = make_float4(0.f, 0.f, 0.f, 0.f);
    float4 a1 = make_float4(0.f, 0.f, 0.f, 0.f);

    int i = 0;
#pragma unroll 4
    for (; i + 1 < n; i += 2) {
        float4 v0 = xp[(size_t)i * (DD / 4)];
        float4 v1 = xp[(size_t)(i + 1) * (DD / 4)];
        a0.x += v0.x; a0.y += v0.y; a0.z += v0.z; a0.w += v0.w;
        a1.x += v1.x; a1.y += v1.y; a1.z += v1.z; a1.w += v1.w;
    }
    if (i < n) {
        float4 v0 = xp[(size_t)i * (DD / 4)];
        a0.x += v0.x; a0.y += v0.y; a0.z += v0.z; a0.w += v0.w;
    }
    a0.x += a1.x; a0.y += a1.y; a0.z += a1.z; a0.w += a1.w;

    g_part[b][sl][t] = a0;
}

// ---------------------------------------------------------------------------
// Kernel 3: one block per (batch, chunk). Deterministic serial sum over the
// chunk's consecutive slice partials (avg ~2), divide, write. Zeros for
// empty/invalid chunks (output is poisoned).
// ---------------------------------------------------------------------------
__global__ void finalize_kernel(float* __restrict__ means,
                                float* __restrict__ cnts_out,
                                int write_cnts) {
    const int c = blockIdx.x;
    const int b = blockIdx.y;
    const int t = threadIdx.x;

    const int cnt = g_chunk_cnt[b][c];
    float4 acc = make_float4(0.f, 0.f, 0.f, 0.f);

    if (cnt > 0) {
        const int st = g_chunk_start[b][c];
        const int n  = g_chunk_nsl[b][c];
        for (int i = 0; i < n; i++) {
            float4 v = g_part[b][st + i][t];
            acc.x += v.x; acc.y += v.y; acc.z += v.z; acc.w += v.w;
        }
        const float inv = 1.0f / (float)cnt;
        acc.x *= inv; acc.y *= inv; acc.z *= inv; acc.w *= inv;
    }

    reinterpret_cast<float4*>(means + ((size_t)b * CC + c) * DD)[t] = acc;

    if (write_cnts && t == 0) {
        cnts_out[b * CC + c] = (float)cnt;
    }
}

extern "C" void kernel_launch(void* const* d_in, const int* in_sizes, int n_in,
                              void* d_out, int out_size) {
    const float* x = nullptr;
    const float* boundaries = nullptr;
    for (int i = 0; i < n_in; i++) {
        if (in_sizes[i] == BB * LL * DD) x = (const float*)d_in[i];
        else if (in_sizes[i] == BB * LL) boundaries = (const float*)d_in[i];
    }

    float* out = (float*)d_out;
    const int means_elems = BB * CC * DD;
    const int write_cnts = (out_size > means_elems) ? 1 : 0;

    seg_scan_kernel<<<BB, 512>>>(boundaries);
    partial_kernel<<<dim3(MAXSL, BB), 256>>>(x);
    finalize_kernel<<<dim3(CC, BB), 256>>>(out, out + means_elems, write_cnts);
}

// round 4
// speedup vs baseline: 1.5285x; 1.0588x over previous
#include <cuda_runtime.h>
#include <cuda_bf16.h>

#define BB 8
#define LL 4096
#define DD 1024
#define CC 128
#define SLICE 32
#define MAXSL (LL / SLICE + CC)   // 256: upper bound on slices per batch

// Packed metadata: one load each.
__device__ int2 g_slice[BB][MAXSL];   // {token start, token end}; {0,0} = unused
__device__ int4 g_chunk[BB][CC];      // {cnt, first slice, n slices, pad}

// Partial sums scratch: 8 * 256 * 256 float4 = 8 MB
__device__ float4 g_part[BB][MAXSL][DD / 4];

// ---------------------------------------------------------------------------
// Kernel 1: per-batch boundary scan -> chunk ranges -> slice list.
// One block per batch, 512 threads (8 tokens each). Hierarchical warp scans.
// ---------------------------------------------------------------------------
__global__ void seg_scan_kernel(const float* __restrict__ boundaries) {
    const int b = blockIdx.x;
    const float* bp = boundaries + (size_t)b * LL;
    const int t    = threadIdx.x;       // 0..511
    const int lane = t & 31;
    const int wid  = t >> 5;            // 0..15

    __shared__ int wsum[16];
    __shared__ int wexcl[16];
    __shared__ int pos[CC + 1];
    __shared__ int snb;
    __shared__ int csum[4];
    __shared__ int cexcl[4];
    __shared__ int snsl;

    // --- phase 1: flags + ordered compaction of boundary positions ---
    const int base = t * 8;
    unsigned flags = 0;
    {
        const float4* bp4 = reinterpret_cast<const float4*>(bp + base);
        float4 v0 = bp4[0];
        float4 v1 = bp4[1];
        if (v0.x > 0.5f) flags |= 1u;
        if (v0.y > 0.5f) flags |= 2u;
        if (v0.z > 0.5f) flags |= 4u;
        if (v0.w > 0.5f) flags |= 8u;
        if (v1.x > 0.5f) flags |= 16u;
        if (v1.y > 0.5f) flags |= 32u;
        if (v1.z > 0.5f) flags |= 64u;
        if (v1.w > 0.5f) flags |= 128u;
    }
    const int cnt = __popc(flags);

    int incl = cnt;
#pragma unroll
    for (int d = 1; d < 32; d <<= 1) {
        int v = __shfl_up_sync(0xFFFFFFFFu, incl, d);
        if (lane >= d) incl += v;
    }
    if (lane == 31) wsum[wid] = incl;
    __syncthreads();

    if (t < 16) {
        int v = wsum[t];
        int iv = v;
#pragma unroll
        for (int d = 1; d < 16; d <<= 1) {
            int u = __shfl_up_sync(0x0000FFFFu, iv, d);
            if (t >= d) iv += u;
        }
        wexcl[t] = iv - v;
        if (t == 15) snb = iv;
    }
    __syncthreads();

    {
        int idx = wexcl[wid] + (incl - cnt);
        unsigned f = flags;
        while (f) {
            int i = __ffs(f) - 1;
            f &= f - 1;
            if (idx <= CC) pos[idx] = base + i;
            idx++;
        }
    }
    __syncthreads();

    const int nb = snb;
    const int valid = nb < CC ? nb : CC;

    // --- phase 2: chunk ranges + slice-count scan (threads 0..127) ---
    int s0 = 0, e0 = 0, len = 0, nsl = 0;
    if (t < CC && t < valid) {
        s0 = pos[t];
        e0 = (t + 1 < nb) ? pos[t + 1] : LL;
        len = e0 - s0;
        nsl = (len + SLICE - 1) / SLICE;
    }

    int cincl = nsl;
#pragma unroll
    for (int d = 1; d < 32; d <<= 1) {
        int v = __shfl_up_sync(0xFFFFFFFFu, cincl, d);
        if (lane >= d) cincl += v;
    }
    if (t < CC && lane == 31) csum[wid] = cincl;
    __syncthreads();

    if (t < 4) {
        int v = csum[t];
        int iv = v;
#pragma unroll
        for (int d = 1; d < 4; d <<= 1) {
            int u = __shfl_up_sync(0x0000000Fu, iv, d);
            if (t >= d) iv += u;
        }
        cexcl[t] = iv - v;
        if (t == 3) snsl = iv;
    }
    __syncthreads();

    const int nsl_total = snsl;

    if (t < CC) {
        const int soff = cexcl[wid] + (cincl - nsl);
        g_chunk[b][t] = make_int4(len, soff, nsl, 0);
        if (len > 0) {
            int si = soff;
            for (int ss = s0; ss < e0; ss += SLICE, si++) {
                int ee = ss + SLICE;
                g_slice[b][si] = make_int2(ss, ee < e0 ? ee : e0);
            }
        }
    }
    // zero-fill unused slice slots so partial_kernel needs no nsl load
    if (t < MAXSL && t >= nsl_total) {
        g_slice[b][t] = make_int2(0, 0);
    }
}

// ---------------------------------------------------------------------------
// Kernel 2 (bandwidth pass): one block per (batch, slice). 256 threads;
// thread t owns float4 column t. Fast path: n==32 fully unrolled for MLP.
// ---------------------------------------------------------------------------
__global__ void __launch_bounds__(256) partial_kernel(const float* __restrict__ x) {
    const int sl = blockIdx.x;
    const int b  = blockIdx.y;
    const int t  = threadIdx.x;

    const int2 se = g_slice[b][sl];
    const int n = se.y - se.x;
    if (n == 0) return;

    const float4* __restrict__ xp =
        reinterpret_cast<const float4*>(x + (size_t)b * LL * DD) +
        (size_t)se.x * (DD / 4) + t;

    float4 a0 = make_float4(0.f, 0.f, 0.f, 0.f);
    float4 a1 = make_float4(0.f, 0.f, 0.f, 0.f);
    float4 a2 = make_float4(0.f, 0.f, 0.f, 0.f);
    float4 a3 = make_float4(0.f, 0.f, 0.f, 0.f);

    if (n == SLICE) {
        // Full slice: compile-time trip count -> deep load batching.
#pragma unroll
        for (int i = 0; i < SLICE; i += 4) {
            float4 v0 = xp[(size_t)(i + 0) * (DD / 4)];
            float4 v1 = xp[(size_t)(i + 1) * (DD / 4)];
            float4 v2 = xp[(size_t)(i + 2) * (DD / 4)];
            float4 v3 = xp[(size_t)(i + 3) * (DD / 4)];
            a0.x += v0.x; a0.y += v0.y; a0.z += v0.z; a0.w += v0.w;
            a1.x += v1.x; a1.y += v1.y; a1.z += v1.z; a1.w += v1.w;
            a2.x += v2.x; a2.y += v2.y; a2.z += v2.z; a2.w += v2.w;
            a3.x += v3.x; a3.y += v3.y; a3.z += v3.z; a3.w += v3.w;
        }
    } else {
        int i = 0;
#pragma unroll 4
        for (; i + 1 < n; i += 2) {
            float4 v0 = xp[(size_t)i * (DD / 4)];
            float4 v1 = xp[(size_t)(i + 1) * (DD / 4)];
            a0.x += v0.x; a0.y += v0.y; a0.z += v0.z; a0.w += v0.w;
            a1.x += v1.x; a1.y += v1.y; a1.z += v1.z; a1.w += v1.w;
        }
        if (i < n) {
            float4 v0 = xp[(size_t)i * (DD / 4)];
            a0.x += v0.x; a0.y += v0.y; a0.z += v0.z; a0.w += v0.w;
        }
    }

    a0.x += a2.x; a0.y += a2.y; a0.z += a2.z; a0.w += a2.w;
    a1.x += a3.x; a1.y += a3.y; a1.z += a3.z; a1.w += a3.w;
    a0.x += a1.x; a0.y += a1.y; a0.z += a1.z; a0.w += a1.w;

    g_part[b][sl][t] = a0;
}

// ---------------------------------------------------------------------------
// Kernel 3: one block per (batch, chunk). Deterministic serial sum over the
// chunk's consecutive slice partials (avg ~2), divide, write.
// ---------------------------------------------------------------------------
__global__ void finalize_kernel(float* __restrict__ means,
                                float* __restrict__ cnts_out,
                                int write_cnts) {
    const int c = blockIdx.x;
    const int b = blockIdx.y;
    const int t = threadIdx.x;

    const int4 meta = g_chunk[b][c];     // {cnt, start, nsl, pad}
    float4 acc = make_float4(0.f, 0.f, 0.f, 0.f);

    if (meta.x > 0) {
        for (int i = 0; i < meta.z; i++) {
            float4 v = g_part[b][meta.y + i][t];
            acc.x += v.x; acc.y += v.y; acc.z += v.z; acc.w += v.w;
        }
        const float inv = 1.0f / (float)meta.x;
        acc.x *= inv; acc.y *= inv; acc.z *= inv; acc.w *= inv;
    }

    reinterpret_cast<float4*>(means + ((size_t)b * CC + c) * DD)[t] = acc;

    if (write_cnts && t == 0) {
        cnts_out[b * CC + c] = (float)meta.x;
    }
}

extern "C" void kernel_launch(void* const* d_in, const int* in_sizes, int n_in,
                              void* d_out, int out_size) {
    const float* x = nullptr;
    const float* boundaries = nullptr;
    for (int i = 0; i < n_in; i++) {
        if (in_sizes[i] == BB * LL * DD) x = (const float*)d_in[i];
        else if (in_sizes[i] == BB * LL) boundaries = (const float*)d_in[i];
    }

    float* out = (float*)d_out;
    const int means_elems = BB * CC * DD;
    const int write_cnts = (out_size > means_elems) ? 1 : 0;

    seg_scan_kernel<<<BB, 512>>>(boundaries);
    partial_kernel<<<dim3(MAXSL, BB), 256>>>(x);
    finalize_kernel<<<dim3(CC, BB), 256>>>(out, out + means_elems, write_cnts);
}

// round 5
// speedup vs baseline: 1.5355x; 1.0046x over previous
#include <cuda_runtime.h>
#include <cuda_bf16.h>

#define BB 8
#define LL 4096
#define DD 1024
#define CC 128
#define SLICE 32
#define MAXSL (LL / SLICE + CC)   // 256: upper bound on slices per batch

// Packed metadata: one load each.
__device__ int4 g_slice[BB][MAXSL];   // {s, e, chunk_id, 0}; s==e => unused
__device__ int4 g_chunk[BB][CC];      // {cnt, first slice, n slices, 0}
__device__ int  g_arrive[BB][CC];     // arrival counters (reset by seg_scan)

// Partial sums scratch (multi-slice chunks only): 8 MB
__device__ float4 g_part[BB][MAXSL][DD / 4];

// ---------------------------------------------------------------------------
// Kernel 1: per-batch boundary scan -> chunk ranges -> slice list.
// Also: resets arrival counters, writes cnts output, zero-fills means for
// empty/invalid chunks (so the pool kernel only touches valid chunks).
// One block per batch, 512 threads. Hierarchical warp scans.
// ---------------------------------------------------------------------------
__global__ void seg_scan_kernel(const float* __restrict__ boundaries,
                                float* __restrict__ means,
                                float* __restrict__ cnts_out,
                                int write_cnts) {
    const int b = blockIdx.x;
    const float* bp = boundaries + (size_t)b * LL;
    const int t    = threadIdx.x;       // 0..511
    const int lane = t & 31;
    const int wid  = t >> 5;            // 0..15

    __shared__ int wsum[16];
    __shared__ int wexcl[16];
    __shared__ int pos[CC + 1];
    __shared__ int snb;
    __shared__ int csum[4];
    __shared__ int cexcl[4];
    __shared__ int snsl;
    __shared__ int elist[CC];           // empty-chunk ids
    __shared__ int s_ne;

    if (t == 0) s_ne = 0;

    // --- phase 1: flags + ordered compaction of boundary positions ---
    const int base = t * 8;
    unsigned flags = 0;
    {
        const float4* bp4 = reinterpret_cast<const float4*>(bp + base);
        float4 v0 = bp4[0];
        float4 v1 = bp4[1];
        if (v0.x > 0.5f) flags |= 1u;
        if (v0.y > 0.5f) flags |= 2u;
        if (v0.z > 0.5f) flags |= 4u;
        if (v0.w > 0.5f) flags |= 8u;
        if (v1.x > 0.5f) flags |= 16u;
        if (v1.y > 0.5f) flags |= 32u;
        if (v1.z > 0.5f) flags |= 64u;
        if (v1.w > 0.5f) flags |= 128u;
    }
    const int cnt = __popc(flags);

    int incl = cnt;
#pragma unroll
    for (int d = 1; d < 32; d <<= 1) {
        int v = __shfl_up_sync(0xFFFFFFFFu, incl, d);
        if (lane >= d) incl += v;
    }
    if (lane == 31) wsum[wid] = incl;
    __syncthreads();

    if (t < 16) {
        int v = wsum[t];
        int iv = v;
#pragma unroll
        for (int d = 1; d < 16; d <<= 1) {
            int u = __shfl_up_sync(0x0000FFFFu, iv, d);
            if (t >= d) iv += u;
        }
        wexcl[t] = iv - v;
        if (t == 15) snb = iv;
    }
    __syncthreads();

    {
        int idx = wexcl[wid] + (incl - cnt);
        unsigned f = flags;
        while (f) {
            int i = __ffs(f) - 1;
            f &= f - 1;
            if (idx <= CC) pos[idx] = base + i;
            idx++;
        }
    }
    __syncthreads();

    const int nb = snb;
    const int valid = nb < CC ? nb : CC;

    // --- phase 2: chunk ranges + slice-count scan (threads 0..127) ---
    int s0 = 0, e0 = 0, len = 0, nsl = 0;
    if (t < CC && t < valid) {
        s0 = pos[t];
        e0 = (t + 1 < nb) ? pos[t + 1] : LL;
        len = e0 - s0;
        nsl = (len + SLICE - 1) / SLICE;
    }

    int cincl = nsl;
#pragma unroll
    for (int d = 1; d < 32; d <<= 1) {
        int v = __shfl_up_sync(0xFFFFFFFFu, cincl, d);
        if (lane >= d) cincl += v;
    }
    if (t < CC && lane == 31) csum[wid] = cincl;
    __syncthreads();

    if (t < 4) {
        int v = csum[t];
        int iv = v;
#pragma unroll
        for (int d = 1; d < 4; d <<= 1) {
            int u = __shfl_up_sync(0x0000000Fu, iv, d);
            if (t >= d) iv += u;
        }
        cexcl[t] = iv - v;
        if (t == 3) snsl = iv;
    }
    __syncthreads();

    const int nsl_total = snsl;

    if (t < CC) {
        const int soff = cexcl[wid] + (cincl - nsl);
        g_chunk[b][t]  = make_int4(len, soff, nsl, 0);
        g_arrive[b][t] = 0;
        if (write_cnts) cnts_out[b * CC + t] = (float)len;
        if (len > 0) {
            int si = soff;
            for (int ss = s0; ss < e0; ss += SLICE, si++) {
                int ee = ss + SLICE;
                g_slice[b][si] = make_int4(ss, ee < e0 ? ee : e0, t, 0);
            }
        } else {
            elist[atomicAdd(&s_ne, 1)] = t;     // empty/invalid chunk
        }
    }
    // zero-fill unused slice slots
    if (t < MAXSL && t >= nsl_total) {
        g_slice[b][t] = make_int4(0, 0, 0, 0);
    }
    __syncthreads();

    // zero means of empty chunks (output buffer is poisoned 0xAA)
    const int ne = s_ne;
    if (t < 256) {
        const float4 z = make_float4(0.f, 0.f, 0.f, 0.f);
        for (int i = 0; i < ne; i++) {
            reinterpret_cast<float4*>(means + ((size_t)b * CC + elist[i]) * DD)[t] = z;
        }
    }
}

// ---------------------------------------------------------------------------
// Kernel 2 (fused pool + finalize): one block per (batch, slice), 256
// threads, thread t owns float4 column t.
//   - single-slice chunk: divide + write mean directly
//   - multi-slice chunk : write partial, last-arriving block reduces the
//     chunk's partials in FIXED slice order (deterministic) and writes mean.
// ---------------------------------------------------------------------------
__global__ void __launch_bounds__(256) pool_finalize_kernel(
        const float* __restrict__ x, float* __restrict__ means) {
    const int sl = blockIdx.x;
    const int b  = blockIdx.y;
    const int t  = threadIdx.x;

    const int4 se = g_slice[b][sl];       // {s, e, chunk, 0}
    const int n = se.y - se.x;
    if (n == 0) return;

    const float4* __restrict__ xp =
        reinterpret_cast<const float4*>(x + (size_t)b * LL * DD) +
        (size_t)se.x * (DD / 4) + t;

    float4 a0 = make_float4(0.f, 0.f, 0.f, 0.f);
    float4 a1 = make_float4(0.f, 0.f, 0.f, 0.f);
    float4 a2 = make_float4(0.f, 0.f, 0.f, 0.f);
    float4 a3 = make_float4(0.f, 0.f, 0.f, 0.f);

    if (n == SLICE) {
#pragma unroll
        for (int i = 0; i < SLICE; i += 4) {
            float4 v0 = xp[(size_t)(i + 0) * (DD / 4)];
            float4 v1 = xp[(size_t)(i + 1) * (DD / 4)];
            float4 v2 = xp[(size_t)(i + 2) * (DD / 4)];
            float4 v3 = xp[(size_t)(i + 3) * (DD / 4)];
            a0.x += v0.x; a0.y += v0.y; a0.z += v0.z; a0.w += v0.w;
            a1.x += v1.x; a1.y += v1.y; a1.z += v1.z; a1.w += v1.w;
            a2.x += v2.x; a2.y += v2.y; a2.z += v2.z; a2.w += v2.w;
            a3.x += v3.x; a3.y += v3.y; a3.z += v3.z; a3.w += v3.w;
        }
    } else {
        int i = 0;
#pragma unroll 4
        for (; i + 1 < n; i += 2) {
            float4 v0 = xp[(size_t)i * (DD / 4)];
            float4 v1 = xp[(size_t)(i + 1) * (DD / 4)];
            a0.x += v0.x; a0.y += v0.y; a0.z += v0.z; a0.w += v0.w;
            a1.x += v1.x; a1.y += v1.y; a1.z += v1.z; a1.w += v1.w;
        }
        if (i < n) {
            float4 v0 = xp[(size_t)i * (DD / 4)];
            a0.x += v0.x; a0.y += v0.y; a0.z += v0.z; a0.w += v0.w;
        }
    }

    a0.x += a2.x; a0.y += a2.y; a0.z += a2.z; a0.w += a2.w;
    a1.x += a3.x; a1.y += a3.y; a1.z += a3.z; a1.w += a3.w;
    a0.x += a1.x; a0.y += a1.y; a0.z += a1.z; a0.w += a1.w;

    const int c = se.z;
    const int4 meta = g_chunk[b][c];      // {cnt, first slice, nsl, 0}

    float4* __restrict__ mp =
        reinterpret_cast<float4*>(means + ((size_t)b * CC + c) * DD);

    if (meta.z == 1) {
        // whole chunk in this slice: finalize directly
        const float inv = 1.0f / (float)n;
        a0.x *= inv; a0.y *= inv; a0.z *= inv; a0.w *= inv;
        mp[t] = a0;
        return;
    }

    // multi-slice: publish partial, last block reduces
    g_part[b][sl][t] = a0;
    __threadfence();
    __syncthreads();

    __shared__ int s_last;
    if (t == 0) {
        s_last = (atomicAdd(&g_arrive[b][c], 1) == meta.z - 1);
    }
    __syncthreads();
    if (!s_last) return;
    __threadfence();

    float4 acc = make_float4(0.f, 0.f, 0.f, 0.f);
    for (int i = 0; i < meta.z; i++) {          // fixed order -> deterministic
        float4 v = g_part[b][meta.y + i][t];
        acc.x += v.x; acc.y += v.y; acc.z += v.z; acc.w += v.w;
    }
    const float inv = 1.0f / (float)meta.x;
    acc.x *= inv; acc.y *= inv; acc.z *= inv; acc.w *= inv;
    mp[t] = acc;
}

extern "C" void kernel_launch(void* const* d_in, const int* in_sizes, int n_in,
                              void* d_out, int out_size) {
    const float* x = nullptr;
    const float* boundaries = nullptr;
    for (int i = 0; i < n_in; i++) {
        if (in_sizes[i] == BB * LL * DD) x = (const float*)d_in[i];
        else if (in_sizes[i] == BB * LL) boundaries = (const float*)d_in[i];
    }

    float* out = (float*)d_out;
    const int means_elems = BB * CC * DD;
    const int write_cnts = (out_size > means_elems) ? 1 : 0;

    seg_scan_kernel<<<BB, 512>>>(boundaries, out, out + means_elems, write_cnts);
    pool_finalize_kernel<<<dim3(MAXSL, BB), 256>>>(x, out);
}

// round 6
// speedup vs baseline: 1.6037x; 1.0444x over previous
#include <cuda_runtime.h>
#include <cuda_bf16.h>

#define BB 8
#define LL 4096
#define DD 1024
#define CC 128
#define SLICE 32
#define MAXSL (LL / SLICE + CC)   // 256 slices max per batch

// Packed metadata
__device__ int4 g_slice[BB][MAXSL];   // {s, e, chunk_id, 0}; s==e => unused
__device__ int4 g_chunk[BB][CC];      // {cnt, first slice, n slices, 0}
__device__ int  g_arrive[BB][CC];     // per-chunk arrival counters (reset by scan)
__device__ int  g_ready[BB];          // per-batch "metadata ready" flags (self-cleaning)
__device__ int  g_done[BB];           // per-batch pool-block completion counters

// Partial sums scratch (multi-slice chunks only): 8 MB
__device__ float4 g_part[BB][MAXSL][DD / 4];

// --- memory-model helpers (generic address space) ---
__device__ __forceinline__ int atomic_add_acq_rel(int* p, int v) {
    int old;
    asm volatile("atom.add.acq_rel.gpu.s32 %0, [%1], %2;"
                 : "=r"(old) : "l"(p), "r"(v) : "memory");
    return old;
}
__device__ __forceinline__ void st_release(int* p, int v) {
    asm volatile("st.release.gpu.s32 [%0], %1;" :: "l"(p), "r"(v) : "memory");
}
__device__ __forceinline__ int ld_acquire(const int* p) {
    int v;
    asm volatile("ld.acquire.gpu.s32 %0, [%1];" : "=r"(v) : "l"(p) : "memory");
    return v;
}

// ---------------------------------------------------------------------------
// One fused kernel, 1D grid of 8 + BB*MAXSL blocks, 256 threads each.
//   bid 0..7      : per-batch boundary scan -> metadata; release ready flag.
//   bid 8..2055   : pool blocks; acquire-spin on ready flag, then pool+finalize.
// ---------------------------------------------------------------------------
__global__ void __launch_bounds__(256) chunk_fused_kernel(
        const float* __restrict__ x,
        const float* __restrict__ boundaries,
        float* __restrict__ means,
        float* __restrict__ cnts_out,
        int write_cnts) {
    const int t    = threadIdx.x;       // 0..255
    const int lane = t & 31;
    const int wid  = t >> 5;            // 0..7

    __shared__ int wsum[8];
    __shared__ int wexcl[8];
    __shared__ int pos[CC + 1];
    __shared__ int snb;
    __shared__ int csum[4];
    __shared__ int cexcl[4];
    __shared__ int snsl;
    __shared__ int elist[CC];
    __shared__ int s_ne;
    __shared__ int s_last;

    if (blockIdx.x < BB) {
        // =================== SCAN BLOCK (one per batch) ====================
        const int b = blockIdx.x;
        const float* bp = boundaries + (size_t)b * LL;
        if (t == 0) s_ne = 0;

        // phase 1: flags (16 tokens/thread) + ordered compaction
        const int base = t * 16;
        unsigned flags = 0;
        {
            const float4* bp4 = reinterpret_cast<const float4*>(bp + base);
#pragma unroll
            for (int q = 0; q < 4; q++) {
                float4 v = bp4[q];
                if (v.x > 0.5f) flags |= 1u << (q * 4 + 0);
                if (v.y > 0.5f) flags |= 1u << (q * 4 + 1);
                if (v.z > 0.5f) flags |= 1u << (q * 4 + 2);
                if (v.w > 0.5f) flags |= 1u << (q * 4 + 3);
            }
        }
        const int cnt = __popc(flags);

        int incl = cnt;
#pragma unroll
        for (int d = 1; d < 32; d <<= 1) {
            int v = __shfl_up_sync(0xFFFFFFFFu, incl, d);
            if (lane >= d) incl += v;
        }
        if (lane == 31) wsum[wid] = incl;
        __syncthreads();

        if (t < 8) {
            int v = wsum[t];
            int iv = v;
#pragma unroll
            for (int d = 1; d < 8; d <<= 1) {
                int u = __shfl_up_sync(0x000000FFu, iv, d);
                if (t >= d) iv += u;
            }
            wexcl[t] = iv - v;
            if (t == 7) snb = iv;
        }
        __syncthreads();

        {
            int idx = wexcl[wid] + (incl - cnt);
            unsigned f = flags;
            while (f) {
                int i = __ffs(f) - 1;
                f &= f - 1;
                if (idx <= CC) pos[idx] = base + i;
                idx++;
            }
        }
        __syncthreads();

        const int nb = snb;
        const int valid = nb < CC ? nb : CC;

        // phase 2: chunk ranges + slice-count scan (threads 0..127 carry data)
        int s0 = 0, e0 = 0, len = 0, nsl = 0;
        if (t < CC && t < valid) {
            s0 = pos[t];
            e0 = (t + 1 < nb) ? pos[t + 1] : LL;
            len = e0 - s0;
            nsl = (len + SLICE - 1) / SLICE;
        }

        int cincl = nsl;
#pragma unroll
        for (int d = 1; d < 32; d <<= 1) {
            int v = __shfl_up_sync(0xFFFFFFFFu, cincl, d);
            if (lane >= d) cincl += v;
        }
        if (t < CC && lane == 31) csum[wid] = cincl;
        __syncthreads();

        if (t < 4) {
            int v = csum[t];
            int iv = v;
#pragma unroll
            for (int d = 1; d < 4; d <<= 1) {
                int u = __shfl_up_sync(0x0000000Fu, iv, d);
                if (t >= d) iv += u;
            }
            cexcl[t] = iv - v;
            if (t == 3) snsl = iv;
        }
        __syncthreads();

        const int nsl_total = snsl;

        if (t < CC) {
            const int soff = cexcl[wid] + (cincl - nsl);
            g_chunk[b][t]  = make_int4(len, soff, nsl, 0);
            g_arrive[b][t] = 0;
            if (write_cnts) cnts_out[b * CC + t] = (float)len;
            if (len > 0) {
                int si = soff;
                for (int ss = s0; ss < e0; ss += SLICE, si++) {
                    int ee = ss + SLICE;
                    g_slice[b][si] = make_int4(ss, ee < e0 ? ee : e0, t, 0);
                }
            } else {
                elist[atomicAdd(&s_ne, 1)] = t;
            }
        }
        if (t >= nsl_total) {                    // zero-fill unused slices
            g_slice[b][t] = make_int4(0, 0, 0, 0);
        }
        __syncthreads();

        // zero means of empty/invalid chunks (output is poisoned 0xAA)
        const int ne = s_ne;
        {
            const float4 z = make_float4(0.f, 0.f, 0.f, 0.f);
            for (int i = 0; i < ne; i++) {
                reinterpret_cast<float4*>(
                    means + ((size_t)b * CC + elist[i]) * DD)[t] = z;
            }
        }
        __syncthreads();

        if (t == 0) st_release(&g_ready[b], 1);   // publish metadata
        return;
    }

    // ======================= POOL BLOCK =======================
    const int idx = blockIdx.x - BB;
    const int b   = idx >> 8;            // / MAXSL
    const int sl  = idx & (MAXSL - 1);

    if (t == 0) {
        while (ld_acquire(&g_ready[b]) == 0) __nanosleep(64);
    }
    __syncthreads();                      // distribute acquire to all threads

    const int4 se = g_slice[b][sl];       // {s, e, chunk, 0}
    const int n = se.y - se.x;

    if (n > 0) {
        const float4* __restrict__ xp =
            reinterpret_cast<const float4*>(x + (size_t)b * LL * DD) +
            (size_t)se.x * (DD / 4) + t;

        float4 a0 = make_float4(0.f, 0.f, 0.f, 0.f);
        float4 a1 = make_float4(0.f, 0.f, 0.f, 0.f);
        float4 a2 = make_float4(0.f, 0.f, 0.f, 0.f);
        float4 a3 = make_float4(0.f, 0.f, 0.f, 0.f);

        if (n == SLICE) {
#pragma unroll
            for (int i = 0; i < SLICE; i += 4) {
                float4 v0 = xp[(size_t)(i + 0) * (DD / 4)];
                float4 v1 = xp[(size_t)(i + 1) * (DD / 4)];
                float4 v2 = xp[(size_t)(i + 2) * (DD / 4)];
                float4 v3 = xp[(size_t)(i + 3) * (DD / 4)];
                a0.x += v0.x; a0.y += v0.y; a0.z += v0.z; a0.w += v0.w;
                a1.x += v1.x; a1.y += v1.y; a1.z += v1.z; a1.w += v1.w;
                a2.x += v2.x; a2.y += v2.y; a2.z += v2.z; a2.w += v2.w;
                a3.x += v3.x; a3.y += v3.y; a3.z += v3.z; a3.w += v3.w;
            }
        } else {
            int i = 0;
#pragma unroll 4
            for (; i + 1 < n; i += 2) {
                float4 v0 = xp[(size_t)i * (DD / 4)];
                float4 v1 = xp[(size_t)(i + 1) * (DD / 4)];
                a0.x += v0.x; a0.y += v0.y; a0.z += v0.z; a0.w += v0.w;
                a1.x += v1.x; a1.y += v1.y; a1.z += v1.z; a1.w += v1.w;
            }
            if (i < n) {
                float4 v0 = xp[(size_t)i * (DD / 4)];
                a0.x += v0.x; a0.y += v0.y; a0.z += v0.z; a0.w += v0.w;
            }
        }

        a0.x += a2.x; a0.y += a2.y; a0.z += a2.z; a0.w += a2.w;
        a1.x += a3.x; a1.y += a3.y; a1.z += a3.z; a1.w += a3.w;
        a0.x += a1.x; a0.y += a1.y; a0.z += a1.z; a0.w += a1.w;

        const int c = se.z;
        const int4 meta = g_chunk[b][c];  // {cnt, first slice, nsl, 0}
        float4* __restrict__ mp =
            reinterpret_cast<float4*>(means + ((size_t)b * CC + c) * DD);

        if (meta.z == 1) {
            const float inv = 1.0f / (float)n;
            a0.x *= inv; a0.y *= inv; a0.z *= inv; a0.w *= inv;
            mp[t] = a0;
        } else {
            // publish partial; one release-atomic per block (no per-thread fences)
            g_part[b][sl][t] = a0;
            __syncthreads();              // intra-CTA HB: all stores before t0's atomic
            if (t == 0) {
                s_last = (atomic_add_acq_rel(&g_arrive[b][c], 1) == meta.z - 1);
            }
            __syncthreads();              // distribute acquire
            if (s_last) {
                float4 acc = make_float4(0.f, 0.f, 0.f, 0.f);
                for (int i = 0; i < meta.z; i++) {   // fixed order: deterministic
                    float4 v = g_part[b][meta.y + i][t];
                    acc.x += v.x; acc.y += v.y; acc.z += v.z; acc.w += v.w;
                }
                const float inv = 1.0f / (float)meta.x;
                acc.x *= inv; acc.y *= inv; acc.z *= inv; acc.w *= inv;
                mp[t] = acc;
            }
        }
    }

    // self-cleaning for graph replay: last pool block of the batch resets flags
    if (t == 0) {
        int old = atomic_add_acq_rel(&g_done[b], 1);
        if (old == MAXSL - 1) {
            g_ready[b] = 0;
            g_done[b]  = 0;
        }
    }
}

extern "C" void kernel_launch(void* const* d_in, const int* in_sizes, int n_in,
                              void* d_out, int out_size) {
    const float* x = nullptr;
    const float* boundaries = nullptr;
    for (int i = 0; i < n_in; i++) {
        if (in_sizes[i] == BB * LL * DD) x = (const float*)d_in[i];
        else if (in_sizes[i] == BB * LL) boundaries = (const float*)d_in[i];
    }

    float* out = (float*)d_out;
    const int means_elems = BB * CC * DD;
    const int write_cnts = (out_size > means_elems) ? 1 : 0;

    chunk_fused_kernel<<<BB + BB * MAXSL, 256>>>(
        x, boundaries, out, out + means_elems, write_cnts);
}